// round 3
// baseline (speedup 1.0000x reference)
#include <cuda_runtime.h>
#include <cstdint>

#define T_TOK 8192
#define HID   2048
#define NEXP  8
#define INTERD 2816
#define GUD   (2*INTERD)      // 5632
#define NSLOT (T_TOK*2)       // 16384

// ---------------- scratch (static device globals; no allocation) -------------
__device__ int   g_counts[NEXP];
__device__ int   g_offsets[NEXP];
__device__ int   g_fill[NEXP];
__device__ int   g_tk_e[NSLOT];        // [t*2+k] expert id
__device__ float g_tk_w[NSLOT];        // [t*2+k] routing weight
__device__ int   g_slot_token[NSLOT];  // slot -> token
__device__ int   g_token_slot[NSLOT];  // [t*2+k] -> slot
__device__ float g_inter[(size_t)NSLOT * INTERD]; // silu(g)*u      (184 MB)
__device__ float g_sout [(size_t)NSLOT * HID];    // down output    (134 MB)

// ---------------- helpers ----------------------------------------------------
__device__ __forceinline__ float to_tf32(float x) {
    uint32_t u;
    asm("cvt.rna.tf32.f32 %0, %1;" : "=r"(u) : "f"(x));
    return __uint_as_float(u);
}

__device__ __forceinline__ void mma_tf32(float c[4], const uint32_t a[4], const uint32_t b[2]) {
    asm volatile(
        "mma.sync.aligned.m16n8k8.row.col.f32.tf32.tf32.f32 "
        "{%0,%1,%2,%3}, {%4,%5,%6,%7}, {%8,%9}, {%0,%1,%2,%3};\n"
        : "+f"(c[0]), "+f"(c[1]), "+f"(c[2]), "+f"(c[3])
        : "r"(a[0]), "r"(a[1]), "r"(a[2]), "r"(a[3]), "r"(b[0]), "r"(b[1]));
}

// ---------------- kernel 0: zero counters ------------------------------------
__global__ void zero_kernel() {
    int i = threadIdx.x;
    if (i < NEXP) { g_counts[i] = 0; g_fill[i] = 0; }
}

// ---------------- kernel 1: router (one block per token) ---------------------
__global__ __launch_bounds__(128)
void router_kernel(const float* __restrict__ x, const float* __restrict__ gw,
                   const float* __restrict__ gb, const float* __restrict__ ebias) {
    const int t = blockIdx.x;
    const float* xr = x + (size_t)t * HID;
    float acc[NEXP];
    #pragma unroll
    for (int e = 0; e < NEXP; e++) acc[e] = 0.f;

    for (int h = threadIdx.x; h < HID; h += 128) {
        float xv = xr[h];
        #pragma unroll
        for (int e = 0; e < NEXP; e++) acc[e] += xv * gw[e * HID + h];
    }
    #pragma unroll
    for (int off = 16; off > 0; off >>= 1) {
        #pragma unroll
        for (int e = 0; e < NEXP; e++)
            acc[e] += __shfl_down_sync(0xffffffffu, acc[e], off);
    }
    __shared__ float ws[4][NEXP];
    int warp = threadIdx.x >> 5, lane = threadIdx.x & 31;
    if (lane == 0) {
        #pragma unroll
        for (int e = 0; e < NEXP; e++) ws[warp][e] = acc[e];
    }
    __syncthreads();
    if (threadIdx.x == 0) {
        float lg[NEXP];
        #pragma unroll
        for (int e = 0; e < NEXP; e++)
            lg[e] = ws[0][e] + ws[1][e] + ws[2][e] + ws[3][e] + gb[e];
        float m = lg[0];
        #pragma unroll
        for (int e = 1; e < NEXP; e++) m = fmaxf(m, lg[e]);
        float p[NEXP], s = 0.f;
        #pragma unroll
        for (int e = 0; e < NEXP; e++) { p[e] = expf(lg[e] - m); s += p[e]; }
        float r[NEXP];
        #pragma unroll
        for (int e = 0; e < NEXP; e++) r[e] = p[e] / s + ebias[e];
        // top-2 (strict > keeps lowest index on ties, matching jax top_k)
        int i0 = 0;
        #pragma unroll
        for (int e = 1; e < NEXP; e++) if (r[e] > r[i0]) i0 = e;
        int i1 = (i0 == 0) ? 1 : 0;
        #pragma unroll
        for (int e = 0; e < NEXP; e++)
            if (e != i0 && r[e] > r[i1]) i1 = e;

        g_tk_e[t * 2 + 0] = i0; g_tk_w[t * 2 + 0] = r[i0];
        g_tk_e[t * 2 + 1] = i1; g_tk_w[t * 2 + 1] = r[i1];
        atomicAdd(&g_counts[i0], 1);
        atomicAdd(&g_counts[i1], 1);
    }
}

// ---------------- kernel 2: prefix -------------------------------------------
__global__ void offsets_kernel() {
    if (threadIdx.x == 0) {
        int s = 0;
        #pragma unroll
        for (int e = 0; e < NEXP; e++) { g_offsets[e] = s; s += g_counts[e]; }
    }
}

// ---------------- kernel 3: scatter tokens to expert buckets ------------------
__global__ void scatter_kernel() {
    int t = blockIdx.x * blockDim.x + threadIdx.x;
    if (t >= T_TOK) return;
    #pragma unroll
    for (int k = 0; k < 2; k++) {
        int e = g_tk_e[t * 2 + k];
        int pos = atomicAdd(&g_fill[e], 1);
        int slot = g_offsets[e] + pos;
        g_slot_token[slot] = t;
        g_token_slot[t * 2 + k] = slot;
    }
}

// ======== GEMM1 fused: inter[slot, 0:2816] = silu(x@Wg^T) * (x@Wu^T) =========
// Block tile: 128 rows x 64 cols, computing BOTH gate and up halves.
#define BM 128
#define BN1 64
#define BK 16
#define SPAD 18

__global__ __launch_bounds__(256)
void gemm1_swiglu(const float* __restrict__ x, const float* __restrict__ Wsrc) {
    const int e = blockIdx.z;
    const int n_e = g_counts[e];
    const int m0 = blockIdx.x * BM;
    if (m0 >= n_e) return;
    const int base = g_offsets[e];
    const int n0 = blockIdx.y * BN1;

    __shared__ float As[BM][SPAD];
    __shared__ float Bs[128][SPAD];   // rows 0..63 gate cols, 64..127 up cols

    const int tid  = threadIdx.x;
    const int warp = tid >> 5;
    const int lane = tid & 31;
    const int wm = warp & 3;    // 4 warps along M (32 rows each)
    const int wn = warp >> 2;   // 2 warps along N (32 cols each)
    const int grp = lane >> 2;  // 0..7
    const int t4  = lane & 3;   // 0..3

    float accg[2][4][4], accu[2][4][4];
    #pragma unroll
    for (int i = 0; i < 2; i++)
        #pragma unroll
        for (int j = 0; j < 4; j++)
            #pragma unroll
            for (int q = 0; q < 4; q++) { accg[i][j][q] = 0.f; accu[i][j][q] = 0.f; }

    const int lrow = tid >> 2;        // 0..63
    const int lk   = (tid & 3) * 4;   // 0,4,8,12

    const float* aptr[2];
    bool avalid[2];
    #pragma unroll
    for (int h = 0; h < 2; h++) {
        int r = m0 + lrow + h * 64;
        avalid[h] = (r < n_e);
        int row = avalid[h] ? g_slot_token[base + r] : 0;
        aptr[h] = x + (size_t)row * HID;
    }
    const float* wbase = Wsrc + (size_t)e * GUD * HID;
    const float* wptr[2];
    wptr[0] = wbase + (size_t)(n0 + lrow) * HID;             // gate rows
    wptr[1] = wbase + (size_t)(INTERD + n0 + lrow) * HID;    // up rows

    for (int k0 = 0; k0 < HID; k0 += BK) {
        #pragma unroll
        for (int h = 0; h < 2; h++) {
            int row = lrow + h * 64;
            float4 v = make_float4(0.f, 0.f, 0.f, 0.f);
            if (avalid[h]) v = *(const float4*)(aptr[h] + k0 + lk);
            As[row][lk + 0] = to_tf32(v.x);
            As[row][lk + 1] = to_tf32(v.y);
            As[row][lk + 2] = to_tf32(v.z);
            As[row][lk + 3] = to_tf32(v.w);
            float4 w = *(const float4*)(wptr[h] + k0 + lk);
            Bs[row][lk + 0] = to_tf32(w.x);
            Bs[row][lk + 1] = to_tf32(w.y);
            Bs[row][lk + 2] = to_tf32(w.z);
            Bs[row][lk + 3] = to_tf32(w.w);
        }
        __syncthreads();
        #pragma unroll
        for (int ks = 0; ks < 2; ks++) {
            const int kk = ks * 8;
            uint32_t af[2][4];
            #pragma unroll
            for (int mi = 0; mi < 2; mi++) {
                int rrow = wm * 32 + mi * 16 + grp;
                af[mi][0] = __float_as_uint(As[rrow    ][kk + t4    ]);
                af[mi][1] = __float_as_uint(As[rrow + 8][kk + t4    ]);
                af[mi][2] = __float_as_uint(As[rrow    ][kk + t4 + 4]);
                af[mi][3] = __float_as_uint(As[rrow + 8][kk + t4 + 4]);
            }
            uint32_t bg[4][2], bu[4][2];
            #pragma unroll
            for (int ni = 0; ni < 4; ni++) {
                int col = wn * 32 + ni * 8 + grp;
                bg[ni][0] = __float_as_uint(Bs[col     ][kk + t4    ]);
                bg[ni][1] = __float_as_uint(Bs[col     ][kk + t4 + 4]);
                bu[ni][0] = __float_as_uint(Bs[col + 64][kk + t4    ]);
                bu[ni][1] = __float_as_uint(Bs[col + 64][kk + t4 + 4]);
            }
            #pragma unroll
            for (int mi = 0; mi < 2; mi++)
                #pragma unroll
                for (int ni = 0; ni < 4; ni++) {
                    mma_tf32(accg[mi][ni], af[mi], bg[ni]);
                    mma_tf32(accu[mi][ni], af[mi], bu[ni]);
                }
        }
        __syncthreads();
    }

    // epilogue: silu(g) * u, elementwise in registers
    #pragma unroll
    for (int mi = 0; mi < 2; mi++) {
        #pragma unroll
        for (int rh = 0; rh < 2; rh++) {
            int rloc = wm * 32 + mi * 16 + grp + rh * 8;
            int r = m0 + rloc;
            if (r >= n_e) continue;
            float* crow = g_inter + (size_t)(base + r) * INTERD + n0;
            #pragma unroll
            for (int ni = 0; ni < 4; ni++) {
                int c = wn * 32 + ni * 8 + 2 * t4;
                float g0 = accg[mi][ni][rh * 2 + 0];
                float g1 = accg[mi][ni][rh * 2 + 1];
                float u0 = accu[mi][ni][rh * 2 + 0];
                float u1 = accu[mi][ni][rh * 2 + 1];
                float2 v;
                v.x = g0 / (1.f + expf(-g0)) * u0;
                v.y = g1 / (1.f + expf(-g1)) * u1;
                *(float2*)(crow + c) = v;
            }
        }
    }
}

// ======== GEMM2: sout[slot, 0:2048] = inter @ w_down[e]^T =====================
#define BN2 128

__global__ __launch_bounds__(256)
void gemm2_down(const float* __restrict__ Wsrc) {
    const int e = blockIdx.z;
    const int n_e = g_counts[e];
    const int m0 = blockIdx.x * BM;
    if (m0 >= n_e) return;
    const int base = g_offsets[e];
    const int n0 = blockIdx.y * BN2;

    __shared__ float As[BM][SPAD];
    __shared__ float Bs[BN2][SPAD];

    const int tid  = threadIdx.x;
    const int warp = tid >> 5;
    const int lane = tid & 31;
    const int wm = warp & 3;
    const int wn = warp >> 2;
    const int grp = lane >> 2;
    const int t4  = lane & 3;

    float acc[2][8][4];
    #pragma unroll
    for (int i = 0; i < 2; i++)
        #pragma unroll
        for (int j = 0; j < 8; j++)
            #pragma unroll
            for (int q = 0; q < 4; q++) acc[i][j][q] = 0.f;

    const int lrow = tid >> 2;
    const int lk   = (tid & 3) * 4;

    const float* aptr[2];
    bool avalid[2];
    #pragma unroll
    for (int h = 0; h < 2; h++) {
        int r = m0 + lrow + h * 64;
        avalid[h] = (r < n_e);
        aptr[h] = g_inter + (size_t)(avalid[h] ? (base + r) : 0) * INTERD;
    }
    const float* wptr[2];
    #pragma unroll
    for (int h = 0; h < 2; h++)
        wptr[h] = Wsrc + (size_t)e * HID * INTERD + (size_t)(n0 + lrow + h * 64) * INTERD;

    for (int k0 = 0; k0 < INTERD; k0 += BK) {
        #pragma unroll
        for (int h = 0; h < 2; h++) {
            int row = lrow + h * 64;
            float4 v = make_float4(0.f, 0.f, 0.f, 0.f);
            if (avalid[h]) v = *(const float4*)(aptr[h] + k0 + lk);
            As[row][lk + 0] = to_tf32(v.x);
            As[row][lk + 1] = to_tf32(v.y);
            As[row][lk + 2] = to_tf32(v.z);
            As[row][lk + 3] = to_tf32(v.w);
            float4 w = *(const float4*)(wptr[h] + k0 + lk);
            Bs[row][lk + 0] = to_tf32(w.x);
            Bs[row][lk + 1] = to_tf32(w.y);
            Bs[row][lk + 2] = to_tf32(w.z);
            Bs[row][lk + 3] = to_tf32(w.w);
        }
        __syncthreads();
        #pragma unroll
        for (int ks = 0; ks < 2; ks++) {
            const int kk = ks * 8;
            uint32_t af[2][4];
            #pragma unroll
            for (int mi = 0; mi < 2; mi++) {
                int rrow = wm * 32 + mi * 16 + grp;
                af[mi][0] = __float_as_uint(As[rrow    ][kk + t4    ]);
                af[mi][1] = __float_as_uint(As[rrow + 8][kk + t4    ]);
                af[mi][2] = __float_as_uint(As[rrow    ][kk + t4 + 4]);
                af[mi][3] = __float_as_uint(As[rrow + 8][kk + t4 + 4]);
            }
            uint32_t bf[8][2];
            #pragma unroll
            for (int ni = 0; ni < 8; ni++) {
                int col = wn * 64 + ni * 8 + grp;
                bf[ni][0] = __float_as_uint(Bs[col][kk + t4    ]);
                bf[ni][1] = __float_as_uint(Bs[col][kk + t4 + 4]);
            }
            #pragma unroll
            for (int mi = 0; mi < 2; mi++)
                #pragma unroll
                for (int ni = 0; ni < 8; ni++)
                    mma_tf32(acc[mi][ni], af[mi], bf[ni]);
        }
        __syncthreads();
    }

    #pragma unroll
    for (int mi = 0; mi < 2; mi++) {
        #pragma unroll
        for (int rh = 0; rh < 2; rh++) {
            int rloc = wm * 32 + mi * 16 + grp + rh * 8;
            int r = m0 + rloc;
            if (r >= n_e) continue;
            float* crow = g_sout + (size_t)(base + r) * HID + n0;
            #pragma unroll
            for (int ni = 0; ni < 8; ni++) {
                int c = wn * 64 + ni * 8 + 2 * t4;
                float2 v;
                v.x = acc[mi][ni][rh * 2 + 0];
                v.y = acc[mi][ni][rh * 2 + 1];
                *(float2*)(crow + c) = v;
            }
        }
    }
}

// ---------------- combine top-2 expert outputs ---------------------------------
__global__ __launch_bounds__(256)
void combine_kernel(float* __restrict__ out) {
    const int t = blockIdx.x;
    const int s0 = g_token_slot[t * 2 + 0];
    const int s1 = g_token_slot[t * 2 + 1];
    const float w0 = g_tk_w[t * 2 + 0];
    const float w1 = g_tk_w[t * 2 + 1];
    const float4* a = (const float4*)(g_sout + (size_t)s0 * HID);
    const float4* b = (const float4*)(g_sout + (size_t)s1 * HID);
    float4* o = (float4*)(out + (size_t)t * HID);
    for (int i = threadIdx.x; i < HID / 4; i += 256) {
        float4 va = a[i], vb = b[i], vo;
        vo.x = w0 * va.x + w1 * vb.x;
        vo.y = w0 * va.y + w1 * vb.y;
        vo.z = w0 * va.z + w1 * vb.z;
        vo.w = w0 * va.w + w1 * vb.w;
        o[i] = vo;
    }
}

// ---------------- launch ------------------------------------------------------
extern "C" void kernel_launch(void* const* d_in, const int* in_sizes, int n_in,
                              void* d_out, int out_size) {
    // Bind inputs by element count (robust to metadata ordering).
    const float *x = 0, *gw = 0, *gb = 0, *ebias = 0, *w_gu = 0, *w_dn = 0;
    for (int i = 0; i < n_in; i++) {
        long s = in_sizes[i];
        const float* p = (const float*)d_in[i];
        if      (s == (long)T_TOK * HID)        x    = p;   // 16,777,216
        else if (s == (long)NEXP * HID)         gw   = p;   // 16,384
        else if (s == (long)NEXP * GUD * HID)   w_gu = p;   // 92,274,688
        else if (s == (long)NEXP * HID * INTERD) w_dn = p;  // 46,137,344
        else if (s == NEXP) { if (!gb) gb = p; else ebias = p; }
    }
    float* out = (float*)d_out;

    zero_kernel<<<1, 32>>>();
    router_kernel<<<T_TOK, 128>>>(x, gw, gb, ebias);
    offsets_kernel<<<1, 32>>>();
    scatter_kernel<<<T_TOK / 256, 256>>>();

    // GEMM1 + SwiGLU fused: grid covers worst-case 16384 rows per expert
    gemm1_swiglu<<<dim3(NSLOT / BM, INTERD / BN1, NEXP), 256>>>(x, w_gu);

    // GEMM2
    gemm2_down<<<dim3(NSLOT / BM, HID / BN2, NEXP), 256>>>(w_dn);

    // Combine
    combine_kernel<<<T_TOK, 256>>>(out);
}

// round 4
// speedup vs baseline: 1.6377x; 1.6377x over previous
#include <cuda_runtime.h>
#include <cstdint>

#define T_TOK 8192
#define HID   2048
#define NEXP  8
#define INTERD 2816
#define GUD   (2*INTERD)      // 5632
#define NSLOT (T_TOK*2)       // 16384

#define BM 128
#define BN1 64
#define BN2 128
#define BK 16
#define SPAD 20               // floats per smem row (16B-aligned rows for cp.async)
#define STAGES 3
#define STAGE_F (256*SPAD)    // As(128xSPAD) + Bs(128xSPAD) floats per stage
#define SMEM_BYTES (STAGES*STAGE_F*4)

// ---------------- scratch (static device globals; no allocation) -------------
__device__ int   g_counts[NEXP];
__device__ int   g_offsets[NEXP];
__device__ int   g_fill[NEXP];
__device__ int   g_tk_e[NSLOT];
__device__ float g_tk_w[NSLOT];
__device__ int   g_slot_token[NSLOT];
__device__ int   g_token_slot[NSLOT];
__device__ float g_inter[(size_t)NSLOT * INTERD]; // 184 MB
__device__ float g_sout [(size_t)NSLOT * HID];    // 134 MB

// ---------------- helpers ----------------------------------------------------
__device__ __forceinline__ float to_tf32(float x) {
    uint32_t u;
    asm("cvt.rna.tf32.f32 %0, %1;" : "=r"(u) : "f"(x));
    return __uint_as_float(u);
}

__device__ __forceinline__ uint32_t tf32_of(const float* p) {
    uint32_t u;
    asm("cvt.rna.tf32.f32 %0, %1;" : "=r"(u) : "f"(*p));
    return u;
}

__device__ __forceinline__ void mma_tf32(float c[4], const uint32_t a[4], const uint32_t b[2]) {
    asm volatile(
        "mma.sync.aligned.m16n8k8.row.col.f32.tf32.tf32.f32 "
        "{%0,%1,%2,%3}, {%4,%5,%6,%7}, {%8,%9}, {%0,%1,%2,%3};\n"
        : "+f"(c[0]), "+f"(c[1]), "+f"(c[2]), "+f"(c[3])
        : "r"(a[0]), "r"(a[1]), "r"(a[2]), "r"(a[3]), "r"(b[0]), "r"(b[1]));
}

__device__ __forceinline__ uint32_t sptr(const void* p) {
    return (uint32_t)__cvta_generic_to_shared(p);
}

// 16B global->shared async copy; sz = 16 (copy) or 0 (zero-fill)
__device__ __forceinline__ void cp16(uint32_t dst, const void* src, int sz) {
    asm volatile("cp.async.cg.shared.global [%0], [%1], 16, %2;\n"
                 :: "r"(dst), "l"(src), "r"(sz));
}
__device__ __forceinline__ void cp_commit() {
    asm volatile("cp.async.commit_group;\n");
}
__device__ __forceinline__ void cp_wait1() {
    asm volatile("cp.async.wait_group 1;\n");
}

// ---------------- kernel 0: zero counters ------------------------------------
__global__ void zero_kernel() {
    int i = threadIdx.x;
    if (i < NEXP) { g_counts[i] = 0; g_fill[i] = 0; }
}

// ---------------- kernel 1: router -------------------------------------------
__global__ __launch_bounds__(128)
void router_kernel(const float* __restrict__ x, const float* __restrict__ gw,
                   const float* __restrict__ gb, const float* __restrict__ ebias) {
    const int t = blockIdx.x;
    const float* xr = x + (size_t)t * HID;
    float acc[NEXP];
    #pragma unroll
    for (int e = 0; e < NEXP; e++) acc[e] = 0.f;

    for (int h = threadIdx.x; h < HID; h += 128) {
        float xv = xr[h];
        #pragma unroll
        for (int e = 0; e < NEXP; e++) acc[e] += xv * gw[e * HID + h];
    }
    #pragma unroll
    for (int off = 16; off > 0; off >>= 1) {
        #pragma unroll
        for (int e = 0; e < NEXP; e++)
            acc[e] += __shfl_down_sync(0xffffffffu, acc[e], off);
    }
    __shared__ float ws[4][NEXP];
    int warp = threadIdx.x >> 5, lane = threadIdx.x & 31;
    if (lane == 0) {
        #pragma unroll
        for (int e = 0; e < NEXP; e++) ws[warp][e] = acc[e];
    }
    __syncthreads();
    if (threadIdx.x == 0) {
        float lg[NEXP];
        #pragma unroll
        for (int e = 0; e < NEXP; e++)
            lg[e] = ws[0][e] + ws[1][e] + ws[2][e] + ws[3][e] + gb[e];
        float m = lg[0];
        #pragma unroll
        for (int e = 1; e < NEXP; e++) m = fmaxf(m, lg[e]);
        float p[NEXP], s = 0.f;
        #pragma unroll
        for (int e = 0; e < NEXP; e++) { p[e] = expf(lg[e] - m); s += p[e]; }
        float r[NEXP];
        #pragma unroll
        for (int e = 0; e < NEXP; e++) r[e] = p[e] / s + ebias[e];
        int i0 = 0;
        #pragma unroll
        for (int e = 1; e < NEXP; e++) if (r[e] > r[i0]) i0 = e;
        int i1 = (i0 == 0) ? 1 : 0;
        #pragma unroll
        for (int e = 0; e < NEXP; e++)
            if (e != i0 && r[e] > r[i1]) i1 = e;

        g_tk_e[t * 2 + 0] = i0; g_tk_w[t * 2 + 0] = r[i0];
        g_tk_e[t * 2 + 1] = i1; g_tk_w[t * 2 + 1] = r[i1];
        atomicAdd(&g_counts[i0], 1);
        atomicAdd(&g_counts[i1], 1);
    }
}

// ---------------- kernel 2: prefix -------------------------------------------
__global__ void offsets_kernel() {
    if (threadIdx.x == 0) {
        int s = 0;
        #pragma unroll
        for (int e = 0; e < NEXP; e++) { g_offsets[e] = s; s += g_counts[e]; }
    }
}

// ---------------- kernel 3: scatter -------------------------------------------
__global__ void scatter_kernel() {
    int t = blockIdx.x * blockDim.x + threadIdx.x;
    if (t >= T_TOK) return;
    #pragma unroll
    for (int k = 0; k < 2; k++) {
        int e = g_tk_e[t * 2 + k];
        int pos = atomicAdd(&g_fill[e], 1);
        int slot = g_offsets[e] + pos;
        g_slot_token[slot] = t;
        g_token_slot[t * 2 + k] = slot;
    }
}

// ======== GEMM1 fused: inter = silu(x@Wg^T) * (x@Wu^T), cp.async 3-stage =====
__global__ __launch_bounds__(256, 2)
void gemm1_swiglu(const float* __restrict__ x, const float* __restrict__ Wsrc) {
    extern __shared__ float sm[];
    const int e = blockIdx.z;
    const int n_e = g_counts[e];
    const int m0 = blockIdx.x * BM;
    if (m0 >= n_e) return;
    const int base = g_offsets[e];
    const int n0 = blockIdx.y * BN1;

    const int tid  = threadIdx.x;
    const int warp = tid >> 5;
    const int lane = tid & 31;
    const int wm = warp & 3;
    const int wn = warp >> 2;
    const int grp = lane >> 2;
    const int t4  = lane & 3;

    float accg[2][4][4], accu[2][4][4];
    #pragma unroll
    for (int i = 0; i < 2; i++)
        #pragma unroll
        for (int j = 0; j < 4; j++)
            #pragma unroll
            for (int q = 0; q < 4; q++) { accg[i][j][q] = 0.f; accu[i][j][q] = 0.f; }

    const int lrow = tid >> 2;        // 0..63
    const int lk   = (tid & 3) * 4;   // 0,4,8,12

    const float* aptr[2]; int asz[2];
    #pragma unroll
    for (int h = 0; h < 2; h++) {
        int r = m0 + lrow + h * 64;
        bool v = (r < n_e);
        asz[h] = v ? 16 : 0;
        int row = v ? g_slot_token[base + r] : 0;
        aptr[h] = x + (size_t)row * HID + lk;
    }
    const float* wbase = Wsrc + (size_t)e * GUD * HID;
    const float* wptr[2];
    wptr[0] = wbase + (size_t)(n0 + lrow) * HID + lk;            // gate
    wptr[1] = wbase + (size_t)(INTERD + n0 + lrow) * HID + lk;   // up

    // per-thread smem store offsets (floats) within a stage
    const int sA0 = (lrow      ) * SPAD + lk;
    const int sA1 = (lrow +  64) * SPAD + lk;
    const int sB0 = 128 * SPAD + (lrow      ) * SPAD + lk;
    const int sB1 = 128 * SPAD + (lrow +  64) * SPAD + lk;

    const int NIT = HID / BK;  // 128

    #define G1_ISSUE(it) do {                                            \
        float* st = sm + ((it) % STAGES) * STAGE_F;                      \
        int k0 = (it) * BK;                                              \
        cp16(sptr(st + sA0), aptr[0] + k0, asz[0]);                      \
        cp16(sptr(st + sA1), aptr[1] + k0, asz[1]);                      \
        cp16(sptr(st + sB0), wptr[0] + k0, 16);                          \
        cp16(sptr(st + sB1), wptr[1] + k0, 16);                          \
    } while (0)

    G1_ISSUE(0); cp_commit();
    G1_ISSUE(1); cp_commit();
    cp_wait1();
    __syncthreads();

    for (int it = 0; it < NIT; ++it) {
        if (it + 2 < NIT) G1_ISSUE(it + 2);
        cp_commit();

        const float* As = sm + (it % STAGES) * STAGE_F;
        const float* Bs = As + 128 * SPAD;

        #pragma unroll
        for (int ks = 0; ks < 2; ks++) {
            const int kk = ks * 8;
            uint32_t af[2][4];
            #pragma unroll
            for (int mi = 0; mi < 2; mi++) {
                int rrow = wm * 32 + mi * 16 + grp;
                af[mi][0] = tf32_of(&As[(rrow    ) * SPAD + kk + t4    ]);
                af[mi][1] = tf32_of(&As[(rrow + 8) * SPAD + kk + t4    ]);
                af[mi][2] = tf32_of(&As[(rrow    ) * SPAD + kk + t4 + 4]);
                af[mi][3] = tf32_of(&As[(rrow + 8) * SPAD + kk + t4 + 4]);
            }
            uint32_t bg[4][2], bu[4][2];
            #pragma unroll
            for (int ni = 0; ni < 4; ni++) {
                int col = wn * 32 + ni * 8 + grp;
                bg[ni][0] = tf32_of(&Bs[(col     ) * SPAD + kk + t4    ]);
                bg[ni][1] = tf32_of(&Bs[(col     ) * SPAD + kk + t4 + 4]);
                bu[ni][0] = tf32_of(&Bs[(col + 64) * SPAD + kk + t4    ]);
                bu[ni][1] = tf32_of(&Bs[(col + 64) * SPAD + kk + t4 + 4]);
            }
            #pragma unroll
            for (int mi = 0; mi < 2; mi++)
                #pragma unroll
                for (int ni = 0; ni < 4; ni++) {
                    mma_tf32(accg[mi][ni], af[mi], bg[ni]);
                    mma_tf32(accu[mi][ni], af[mi], bu[ni]);
                }
        }
        cp_wait1();
        __syncthreads();
    }

    // epilogue: silu(g)*u in registers
    #pragma unroll
    for (int mi = 0; mi < 2; mi++) {
        #pragma unroll
        for (int rh = 0; rh < 2; rh++) {
            int rloc = wm * 32 + mi * 16 + grp + rh * 8;
            int r = m0 + rloc;
            if (r >= n_e) continue;
            float* crow = g_inter + (size_t)(base + r) * INTERD + n0;
            #pragma unroll
            for (int ni = 0; ni < 4; ni++) {
                int c = wn * 32 + ni * 8 + 2 * t4;
                float g0 = accg[mi][ni][rh * 2 + 0];
                float g1 = accg[mi][ni][rh * 2 + 1];
                float u0 = accu[mi][ni][rh * 2 + 0];
                float u1 = accu[mi][ni][rh * 2 + 1];
                float2 v;
                v.x = g0 / (1.f + expf(-g0)) * u0;
                v.y = g1 / (1.f + expf(-g1)) * u1;
                *(float2*)(crow + c) = v;
            }
        }
    }
    #undef G1_ISSUE
}

// ======== GEMM2: sout = inter @ w_down[e]^T, cp.async 3-stage =================
__global__ __launch_bounds__(256, 2)
void gemm2_down(const float* __restrict__ Wsrc) {
    extern __shared__ float sm[];
    const int e = blockIdx.z;
    const int n_e = g_counts[e];
    const int m0 = blockIdx.x * BM;
    if (m0 >= n_e) return;
    const int base = g_offsets[e];
    const int n0 = blockIdx.y * BN2;

    const int tid  = threadIdx.x;
    const int warp = tid >> 5;
    const int lane = tid & 31;
    const int wm = warp & 3;
    const int wn = warp >> 2;
    const int grp = lane >> 2;
    const int t4  = lane & 3;

    float acc[2][8][4];
    #pragma unroll
    for (int i = 0; i < 2; i++)
        #pragma unroll
        for (int j = 0; j < 8; j++)
            #pragma unroll
            for (int q = 0; q < 4; q++) acc[i][j][q] = 0.f;

    const int lrow = tid >> 2;
    const int lk   = (tid & 3) * 4;

    const float* aptr[2]; int asz[2];
    #pragma unroll
    for (int h = 0; h < 2; h++) {
        int r = m0 + lrow + h * 64;
        bool v = (r < n_e);
        asz[h] = v ? 16 : 0;
        aptr[h] = g_inter + (size_t)(v ? (base + r) : base) * INTERD + lk;
    }
    const float* wptr[2];
    #pragma unroll
    for (int h = 0; h < 2; h++)
        wptr[h] = Wsrc + (size_t)e * HID * INTERD + (size_t)(n0 + lrow + h * 64) * INTERD + lk;

    const int sA0 = (lrow      ) * SPAD + lk;
    const int sA1 = (lrow +  64) * SPAD + lk;
    const int sB0 = 128 * SPAD + (lrow      ) * SPAD + lk;
    const int sB1 = 128 * SPAD + (lrow +  64) * SPAD + lk;

    const int NIT = INTERD / BK;  // 176

    #define G2_ISSUE(it) do {                                            \
        float* st = sm + ((it) % STAGES) * STAGE_F;                      \
        int k0 = (it) * BK;                                              \
        cp16(sptr(st + sA0), aptr[0] + k0, asz[0]);                      \
        cp16(sptr(st + sA1), aptr[1] + k0, asz[1]);                      \
        cp16(sptr(st + sB0), wptr[0] + k0, 16);                          \
        cp16(sptr(st + sB1), wptr[1] + k0, 16);                          \
    } while (0)

    G2_ISSUE(0); cp_commit();
    G2_ISSUE(1); cp_commit();
    cp_wait1();
    __syncthreads();

    for (int it = 0; it < NIT; ++it) {
        if (it + 2 < NIT) G2_ISSUE(it + 2);
        cp_commit();

        const float* As = sm + (it % STAGES) * STAGE_F;
        const float* Bs = As + 128 * SPAD;

        #pragma unroll
        for (int ks = 0; ks < 2; ks++) {
            const int kk = ks * 8;
            uint32_t af[2][4];
            #pragma unroll
            for (int mi = 0; mi < 2; mi++) {
                int rrow = wm * 32 + mi * 16 + grp;
                af[mi][0] = tf32_of(&As[(rrow    ) * SPAD + kk + t4    ]);
                af[mi][1] = tf32_of(&As[(rrow + 8) * SPAD + kk + t4    ]);
                af[mi][2] = tf32_of(&As[(rrow    ) * SPAD + kk + t4 + 4]);
                af[mi][3] = tf32_of(&As[(rrow + 8) * SPAD + kk + t4 + 4]);
            }
            uint32_t bf[8][2];
            #pragma unroll
            for (int ni = 0; ni < 8; ni++) {
                int col = wn * 64 + ni * 8 + grp;
                bf[ni][0] = tf32_of(&Bs[col * SPAD + kk + t4    ]);
                bf[ni][1] = tf32_of(&Bs[col * SPAD + kk + t4 + 4]);
            }
            #pragma unroll
            for (int mi = 0; mi < 2; mi++)
                #pragma unroll
                for (int ni = 0; ni < 8; ni++)
                    mma_tf32(acc[mi][ni], af[mi], bf[ni]);
        }
        cp_wait1();
        __syncthreads();
    }

    #pragma unroll
    for (int mi = 0; mi < 2; mi++) {
        #pragma unroll
        for (int rh = 0; rh < 2; rh++) {
            int rloc = wm * 32 + mi * 16 + grp + rh * 8;
            int r = m0 + rloc;
            if (r >= n_e) continue;
            float* crow = g_sout + (size_t)(base + r) * HID + n0;
            #pragma unroll
            for (int ni = 0; ni < 8; ni++) {
                int c = wn * 64 + ni * 8 + 2 * t4;
                float2 v;
                v.x = acc[mi][ni][rh * 2 + 0];
                v.y = acc[mi][ni][rh * 2 + 1];
                *(float2*)(crow + c) = v;
            }
        }
    }
    #undef G2_ISSUE
}

// ---------------- combine ------------------------------------------------------
__global__ __launch_bounds__(256)
void combine_kernel(float* __restrict__ out) {
    const int t = blockIdx.x;
    const int s0 = g_token_slot[t * 2 + 0];
    const int s1 = g_token_slot[t * 2 + 1];
    const float w0 = g_tk_w[t * 2 + 0];
    const float w1 = g_tk_w[t * 2 + 1];
    const float4* a = (const float4*)(g_sout + (size_t)s0 * HID);
    const float4* b = (const float4*)(g_sout + (size_t)s1 * HID);
    float4* o = (float4*)(out + (size_t)t * HID);
    for (int i = threadIdx.x; i < HID / 4; i += 256) {
        float4 va = a[i], vb = b[i], vo;
        vo.x = w0 * va.x + w1 * vb.x;
        vo.y = w0 * va.y + w1 * vb.y;
        vo.z = w0 * va.z + w1 * vb.z;
        vo.w = w0 * va.w + w1 * vb.w;
        o[i] = vo;
    }
}

// ---------------- launch ------------------------------------------------------
extern "C" void kernel_launch(void* const* d_in, const int* in_sizes, int n_in,
                              void* d_out, int out_size) {
    const float *x = 0, *gw = 0, *gb = 0, *ebias = 0, *w_gu = 0, *w_dn = 0;
    for (int i = 0; i < n_in; i++) {
        long s = in_sizes[i];
        const float* p = (const float*)d_in[i];
        if      (s == (long)T_TOK * HID)         x    = p;
        else if (s == (long)NEXP * HID)          gw   = p;
        else if (s == (long)NEXP * GUD * HID)    w_gu = p;
        else if (s == (long)NEXP * HID * INTERD) w_dn = p;
        else if (s == NEXP) { if (!gb) gb = p; else ebias = p; }
    }
    float* out = (float*)d_out;

    cudaFuncSetAttribute(gemm1_swiglu, cudaFuncAttributeMaxDynamicSharedMemorySize, SMEM_BYTES);
    cudaFuncSetAttribute(gemm2_down,   cudaFuncAttributeMaxDynamicSharedMemorySize, SMEM_BYTES);

    zero_kernel<<<1, 32>>>();
    router_kernel<<<T_TOK, 128>>>(x, gw, gb, ebias);
    offsets_kernel<<<1, 32>>>();
    scatter_kernel<<<T_TOK / 256, 256>>>();

    gemm1_swiglu<<<dim3(NSLOT / BM, INTERD / BN1, NEXP), 256, SMEM_BYTES>>>(x, w_gu);
    gemm2_down<<<dim3(NSLOT / BM, HID / BN2, NEXP), 256, SMEM_BYTES>>>(w_dn);

    combine_kernel<<<T_TOK, 256>>>(out);
}